// round 9
// baseline (speedup 1.0000x reference)
#include <cuda_runtime.h>
#include <cuda_fp16.h>
#include <cstdint>

#define BB   8
#define CC   256
#define NN   16384

// Scratch (device-global; no allocations allowed)
__device__ __half  g_Kh[(size_t)BB * 256 * NN];  // exp(K + bk), fp16 (64 MB)
__device__ __half  g_Vh[(size_t)BB * 256 * NN];  // V + bv, fp16 (64 MB)
__device__ float    g_s[BB * 256];               // softmax denominators
__device__ uint32_t g_Wh[512 * 128];             // [Wk; Wv] packed half2

// ---------------------------------------------------------------------------
// fp16 mma.sync m16n8k16 (fp32 accumulate)
// ---------------------------------------------------------------------------
__device__ __forceinline__ void mma_f16(float* d, const uint32_t* a,
                                        const uint32_t* b) {
    asm volatile(
        "mma.sync.aligned.m16n8k16.row.col.f32.f16.f16.f32 "
        "{%0,%1,%2,%3}, {%4,%5,%6,%7}, {%8,%9}, {%0,%1,%2,%3};"
        : "+f"(d[0]), "+f"(d[1]), "+f"(d[2]), "+f"(d[3])
        : "r"(a[0]), "r"(a[1]), "r"(a[2]), "r"(a[3]), "r"(b[0]), "r"(b[1]));
}

__device__ __forceinline__ uint32_t pack_h2(float lo, float hi) {
    __half2 h = __floats2half2_rn(lo, hi);
    return *(uint32_t*)&h;
}

#define CPA16(dst, src) \
    asm volatile("cp.async.cg.shared.global [%0], [%1], 16;" \
                 :: "r"(dst), "l"(src) : "memory")
#define CPA_COMMIT() asm volatile("cp.async.commit_group;" ::: "memory")
#define CPA_WAIT1()  asm volatile("cp.async.wait_group 1;" ::: "memory")
#define CPA_WAIT0()  asm volatile("cp.async.wait_group 0;" ::: "memory")

// ---------------------------------------------------------------------------
// K0: zero out + g_s; pack [Wk; Wv] into half2 pairs g_Wh
// ---------------------------------------------------------------------------
__global__ void k0_prep(float* __restrict__ out, int n,
                        const float* __restrict__ Wk,
                        const float* __restrict__ Wv) {
    int i = blockIdx.x * 256 + threadIdx.x;
    if (i < n) out[i] = 0.0f;
    if (i < BB * 256) g_s[i] = 0.0f;
    if (i < 512 * 128) {
        int r = i >> 7, c = (i & 127) * 2;
        const float* W = (r < 256) ? &Wk[r * 256 + c] : &Wv[(r - 256) * 256 + c];
        g_Wh[i] = pack_h2(W[0], W[1]);
    }
}

// ---------------------------------------------------------------------------
// K1: (K|V) = W @ x + bias; K: exp + rowsum fused. fp16 MMA.
// 256 thr (8 warps: 4m x 2n), CTA tile 128x128, chunk 32 channels.
// A: FULL W tile resident (cp.async once, stride 132 u32). B: LDG f32 ->
// cvt f16x2 -> STS, [n][k] stride 20 u32, reg-double-buffered, 1 sync/chunk.
// Epilogue: fragments -> smem stage (stride 68 u32, conflict-free) ->
// coalesced STG.128 (100% sector efficiency).
// grid (4 m-tiles, 128 n-tiles, 8 b), occ 2.
// ---------------------------------------------------------------------------
#define ASTR      132                            // u32 per A row
#define K1_A_B    (128 * ASTR * 4)               // 67584
#define SBU       20                             // u32 per B row
#define K1_B_B    (128 * SBU * 4)                // 10240 per buffer
#define K1_SMEM   (K1_A_B + 2 * K1_B_B)          // 88064
#define DSTR      68                             // u32 per staged D row

__global__ void __launch_bounds__(256, 2)
k1_gemm(const float* __restrict__ x,
        const float* __restrict__ bk, const float* __restrict__ bv) {
    extern __shared__ char sm1[];
    const uint32_t smbase = (uint32_t)__cvta_generic_to_shared(sm1);

    const int tid  = threadIdx.x;
    const int wid  = tid >> 5;
    const int lane = tid & 31;
    const int lr   = lane >> 2, lc = lane & 3;
    const int wm   = (wid & 3) * 32;
    const int wn   = (wid >> 2) * 64;

    const int mtile = blockIdx.x;            // 0..3
    const int n0    = blockIdx.y * 128;
    const int b     = blockIdx.z;
    const bool isK  = (mtile < 2);
    const int mrow0 = (mtile & 1) * 128;

    const uint32_t* Wh0 = g_Wh + (size_t)(mtile * 128) * 128;
    const float* Xb = x + (size_t)b * CC * NN + n0;

    // ---- issue full-A cp.async (128 rows x 128 u32) ----
    #pragma unroll
    for (int p = 0; p < 16; ++p) {
        const int idx = tid + p * 256;
        const int row = idx >> 5, qu = (idx & 31) * 4;
        CPA16(smbase + (uint32_t)(row * ASTR + qu) * 4,
              Wh0 + (size_t)row * 128 + qu);
    }
    CPA_COMMIT();

    const uint32_t* sAu = (const uint32_t*)sm1;
    uint32_t* sB[2] = {(uint32_t*)(sm1 + K1_A_B),
                       (uint32_t*)(sm1 + K1_A_B + K1_B_B)};

    float acc[2][8][4];
    #pragma unroll
    for (int i = 0; i < 2; ++i)
        #pragma unroll
        for (int j = 0; j < 8; ++j)
            #pragma unroll
            for (int t = 0; t < 4; ++t) acc[i][j][t] = 0.0f;

    // B gather: warp wid owns channels c0+4wid..+3, lanes = n
    float bT[4][4];
    const float* Xw = Xb + (size_t)(4 * wid) * NN;

    #pragma unroll
    for (int i2 = 0; i2 < 4; ++i2) {
        const int nl = i2 * 32 + lane;
        bT[i2][0] = Xw[nl];
        bT[i2][1] = Xw[(size_t)NN + nl];
        bT[i2][2] = Xw[2 * (size_t)NN + nl];
        bT[i2][3] = Xw[3 * (size_t)NN + nl];
    }
    CPA_WAIT0();                             // A resident
    #pragma unroll
    for (int i2 = 0; i2 < 4; ++i2) {
        const int nl = i2 * 32 + lane;
        uint32_t* d = sB[0] + nl * SBU + 2 * wid;
        d[0] = pack_h2(bT[i2][0], bT[i2][1]);
        d[1] = pack_h2(bT[i2][2], bT[i2][3]);
    }
    __syncthreads();

    #pragma unroll
    for (int ic = 0; ic < 8; ++ic) {
        if (ic < 7) {
            const float* Xc = Xw + (size_t)(ic + 1) * 32 * NN;
            #pragma unroll
            for (int i2 = 0; i2 < 4; ++i2) {
                const int nl = i2 * 32 + lane;
                bT[i2][0] = Xc[nl];
                bT[i2][1] = Xc[(size_t)NN + nl];
                bT[i2][2] = Xc[2 * (size_t)NN + nl];
                bT[i2][3] = Xc[3 * (size_t)NN + nl];
            }
        }

        const uint32_t* sBu = sB[ic & 1];
        const int abase = ic * 16;
        #pragma unroll
        for (int ks = 0; ks < 2; ++ks) {
            uint32_t a[2][4], bf[8][2];
            #pragma unroll
            for (int i = 0; i < 2; ++i) {
                const int base = (wm + i * 16 + lr) * ASTR + abase + ks * 8 + lc;
                a[i][0] = sAu[base];
                a[i][1] = sAu[base + 8 * ASTR];
                a[i][2] = sAu[base + 4];
                a[i][3] = sAu[base + 8 * ASTR + 4];
            }
            #pragma unroll
            for (int j = 0; j < 8; ++j) {
                const int base = (wn + j * 8 + lr) * SBU + ks * 8 + lc;
                bf[j][0] = sBu[base];
                bf[j][1] = sBu[base + 4];
            }
            #pragma unroll
            for (int i = 0; i < 2; ++i)
                #pragma unroll
                for (int j = 0; j < 8; ++j) mma_f16(acc[i][j], a[i], bf[j]);
        }

        if (ic < 7) {
            uint32_t* d0 = sB[(ic + 1) & 1];
            #pragma unroll
            for (int i2 = 0; i2 < 4; ++i2) {
                const int nl = i2 * 32 + lane;
                uint32_t* d = d0 + nl * SBU + 2 * wid;
                d[0] = pack_h2(bT[i2][0], bT[i2][1]);
                d[1] = pack_h2(bT[i2][2], bT[i2][3]);
            }
        }
        __syncthreads();   // final iter: also fences A-reads before stage reuse
    }

    // ---- Epilogue: fragments -> smem stage -> coalesced STG.128 ----
    const float* bias = isK ? bk : bv;
    __half* gout = isK ? g_Kh : g_Vh;
    uint32_t* stg = (uint32_t*)sm1;          // reuse A region (34816 B used)
    float rs[2][2] = {{0.f, 0.f}, {0.f, 0.f}};

    #pragma unroll
    for (int i = 0; i < 2; ++i) {
        const int row0 = wm + i * 16 + lr;
        const int row1 = row0 + 8;
        const float b0 = bias[mrow0 + row0], b1 = bias[mrow0 + row1];
        #pragma unroll
        for (int j = 0; j < 8; ++j) {
            float v0 = acc[i][j][0] + b0, v1 = acc[i][j][1] + b0;
            float v2 = acc[i][j][2] + b1, v3 = acc[i][j][3] + b1;
            if (isK) {
                v0 = __expf(v0); v1 = __expf(v1);
                v2 = __expf(v2); v3 = __expf(v3);
            }
            uint32_t h0 = pack_h2(v0, v1);
            uint32_t h1 = pack_h2(v2, v3);
            if (isK) {           // rowsum of ROUNDED values (cancels in softmax)
                float2 f0 = __half22float2(*(__half2*)&h0);
                float2 f1 = __half22float2(*(__half2*)&h1);
                rs[i][0] += f0.x + f0.y;
                rs[i][1] += f1.x + f1.y;
            }
            const int cu = (wn >> 1) + j * 4 + lc;   // u32 column
            stg[row0 * DSTR + cu] = h0;
            stg[row1 * DSTR + cu] = h1;
        }
    }
    __syncthreads();

    // Coalesced write: 2 threads per row, 32 u32 each (8 x STG.128)
    {
        const int row = tid >> 1;
        const int half = (tid & 1) * 32;
        const uint32_t* src = stg + row * DSTR + half;
        uint32_t* dst = (uint32_t*)(gout + ((size_t)b * 256 + mrow0 + row) * NN
                                    + n0) + half;
        #pragma unroll
        for (int it = 0; it < 8; ++it) {
            uint4 v = *(const uint4*)(src + it * 4);
            *(uint4*)(dst + it * 4) = v;
        }
    }

    if (isK) {
        #pragma unroll
        for (int i = 0; i < 2; ++i)
            #pragma unroll
            for (int h = 0; h < 2; ++h) {
                float v = rs[i][h];
                v += __shfl_xor_sync(0xffffffffu, v, 1);
                v += __shfl_xor_sync(0xffffffffu, v, 2);
                if (lc == 0) {
                    int ch = mrow0 + wm + i * 16 + lr + h * 8;
                    atomicAdd(&g_s[b * 256 + ch], v);
                }
            }
    }
}

// ---------------------------------------------------------------------------
// K3: context = (1/s) * expK @ V^T, all fp16 operands, f32 acc.
// 256 thr, warp tile 32x64, CTA 128x128, chunk 32 spatial, 3-stage ring,
// contraction split 8 ways. grid (4 tiles, 8 splits, 8 b). (unchanged R8)
// ---------------------------------------------------------------------------
#define SA3U      20
#define K3_T_B    (128 * SA3U * 4)              // 10240 per tile
#define K3_STG    (2 * K3_T_B)                  // 20480 bytes/stage
#define K3_SMEM   (3 * K3_STG)                  // 61440

__device__ __forceinline__ void k3_prefetch(uint32_t smbase, int st,
                                            const __half* Kb, const __half* Vb,
                                            int c0, int tid) {
    const uint32_t sA = smbase + (uint32_t)(st * K3_STG);
    const uint32_t sB = sA + K3_T_B;
    #pragma unroll
    for (int p = 0; p < 2; ++p) {
        const int idx = tid + p * 256;
        const int row = idx >> 2, qu = (idx & 3) * 4;
        const uint32_t off = (uint32_t)(row * SA3U + qu) * 4;
        CPA16(sA + off, Kb + (size_t)row * NN + c0 + qu * 2);
        CPA16(sB + off, Vb + (size_t)row * NN + c0 + qu * 2);
    }
}

__global__ void __launch_bounds__(256, 2)
k3_context(float* __restrict__ out) {
    extern __shared__ char sm3[];
    const uint32_t smbase = (uint32_t)__cvta_generic_to_shared(sm3);

    const int tid  = threadIdx.x;
    const int wid  = tid >> 5;
    const int lane = tid & 31;
    const int lr   = lane >> 2, lc = lane & 3;
    const int wm   = (wid & 3) * 32;
    const int wn   = (wid >> 2) * 64;

    const int km0 = (blockIdx.x & 1) * 128;
    const int vm0 = (blockIdx.x >> 1) * 128;
    const int nb  = blockIdx.y * 2048;
    const int b   = blockIdx.z;

    const __half* Kb = g_Kh + ((size_t)b * 256 + km0) * NN + nb;
    const __half* Vb = g_Vh + ((size_t)b * 256 + vm0) * NN + nb;

    float acc[2][8][4];
    #pragma unroll
    for (int i = 0; i < 2; ++i)
        #pragma unroll
        for (int j = 0; j < 8; ++j)
            #pragma unroll
            for (int t = 0; t < 4; ++t) acc[i][j][t] = 0.0f;

    k3_prefetch(smbase, 0, Kb, Vb, 0, tid);
    CPA_COMMIT();
    k3_prefetch(smbase, 1, Kb, Vb, 32, tid);
    CPA_COMMIT();

    for (int ic = 0; ic < 64; ++ic) {
        CPA_WAIT1();
        __syncthreads();
        const uint32_t* sAu = (const uint32_t*)(sm3 + (ic % 3) * K3_STG);
        const uint32_t* sBu = (const uint32_t*)(sm3 + (ic % 3) * K3_STG + K3_T_B);

        #pragma unroll
        for (int ks = 0; ks < 2; ++ks) {
            uint32_t a[2][4], bf[8][2];
            #pragma unroll
            for (int i = 0; i < 2; ++i) {
                const int base = (wm + i * 16 + lr) * SA3U + ks * 8 + lc;
                a[i][0] = sAu[base];
                a[i][1] = sAu[base + 8 * SA3U];
                a[i][2] = sAu[base + 4];
                a[i][3] = sAu[base + 8 * SA3U + 4];
            }
            #pragma unroll
            for (int j = 0; j < 8; ++j) {
                const int base = (wn + j * 8 + lr) * SA3U + ks * 8 + lc;
                bf[j][0] = sBu[base];
                bf[j][1] = sBu[base + 4];
            }
            #pragma unroll
            for (int i = 0; i < 2; ++i)
                #pragma unroll
                for (int j = 0; j < 8; ++j) mma_f16(acc[i][j], a[i], bf[j]);
        }

        if (ic + 2 < 64)
            k3_prefetch(smbase, (ic + 2) % 3, Kb, Vb, (ic + 2) * 32, tid);
        CPA_COMMIT();
    }

    #pragma unroll
    for (int i = 0; i < 2; ++i) {
        const int k0r = km0 + wm + i * 16 + lr;
        const int k1r = k0r + 8;
        const float inv0 = 1.0f / g_s[b * 256 + k0r];
        const float inv1 = 1.0f / g_s[b * 256 + k1r];
        float* r0 = out + ((size_t)b * 256 + k0r) * 256 + vm0 + wn + 2 * lc;
        float* r1 = out + ((size_t)b * 256 + k1r) * 256 + vm0 + wn + 2 * lc;
        #pragma unroll
        for (int j = 0; j < 8; ++j) {
            atomicAdd(r0 + j * 8,     acc[i][j][0] * inv0);
            atomicAdd(r0 + j * 8 + 1, acc[i][j][1] * inv0);
            atomicAdd(r1 + j * 8,     acc[i][j][2] * inv1);
            atomicAdd(r1 + j * 8 + 1, acc[i][j][3] * inv1);
        }
    }
}

// ---------------------------------------------------------------------------
// Launch
// ---------------------------------------------------------------------------
extern "C" void kernel_launch(void* const* d_in, const int* in_sizes, int n_in,
                              void* d_out, int out_size) {
    const float* x  = (const float*)d_in[0];
    const float* Wk = (const float*)d_in[1];
    const float* bk = (const float*)d_in[2];
    const float* Wv = (const float*)d_in[3];
    const float* bv = (const float*)d_in[4];
    float* out = (float*)d_out;

    cudaFuncSetAttribute(k1_gemm, cudaFuncAttributeMaxDynamicSharedMemorySize,
                         K1_SMEM);
    cudaFuncSetAttribute(k3_context, cudaFuncAttributeMaxDynamicSharedMemorySize,
                         K3_SMEM);

    k0_prep<<<(out_size + 255) / 256, 256>>>(out, out_size, Wk, Wv);

    dim3 g1(4, 128, BB);
    k1_gemm<<<g1, 256, K1_SMEM>>>(x, bk, bv);

    dim3 g3(4, 8, BB);
    k3_context<<<g3, 256, K3_SMEM>>>(out);
}

// round 10
// speedup vs baseline: 1.0744x; 1.0744x over previous
#include <cuda_runtime.h>
#include <cuda_fp16.h>
#include <cstdint>

#define BB   8
#define CC   256
#define NN   16384

// Scratch (device-global; no allocations allowed)
__device__ __half  g_Kh[(size_t)BB * 256 * NN];  // exp(K + bk), fp16 (64 MB)
__device__ __half  g_Vh[(size_t)BB * 256 * NN];  // V + bv, fp16 (64 MB)
__device__ float    g_s[BB * 256];               // softmax denominators
__device__ uint32_t g_Wh[512 * 128];             // [Wk; Wv] packed half2

// ---------------------------------------------------------------------------
// fp16 mma.sync m16n8k16 (fp32 accumulate)
// ---------------------------------------------------------------------------
__device__ __forceinline__ void mma_f16(float* d, const uint32_t* a,
                                        const uint32_t* b) {
    asm volatile(
        "mma.sync.aligned.m16n8k16.row.col.f32.f16.f16.f32 "
        "{%0,%1,%2,%3}, {%4,%5,%6,%7}, {%8,%9}, {%0,%1,%2,%3};"
        : "+f"(d[0]), "+f"(d[1]), "+f"(d[2]), "+f"(d[3])
        : "r"(a[0]), "r"(a[1]), "r"(a[2]), "r"(a[3]), "r"(b[0]), "r"(b[1]));
}

__device__ __forceinline__ uint32_t pack_h2(float lo, float hi) {
    __half2 h = __floats2half2_rn(lo, hi);
    return *(uint32_t*)&h;
}

#define CPA16(dst, src) \
    asm volatile("cp.async.cg.shared.global [%0], [%1], 16;" \
                 :: "r"(dst), "l"(src) : "memory")
#define CPA_COMMIT() asm volatile("cp.async.commit_group;" ::: "memory")
#define CPA_WAIT1()  asm volatile("cp.async.wait_group 1;" ::: "memory")
#define CPA_WAIT0()  asm volatile("cp.async.wait_group 0;" ::: "memory")

// ---------------------------------------------------------------------------
// K0: zero out + g_s; pack [Wk; Wv] into half2 pairs g_Wh
// ---------------------------------------------------------------------------
__global__ void k0_prep(float* __restrict__ out, int n,
                        const float* __restrict__ Wk,
                        const float* __restrict__ Wv) {
    int i = blockIdx.x * 256 + threadIdx.x;
    if (i < n) out[i] = 0.0f;
    if (i < BB * 256) g_s[i] = 0.0f;
    if (i < 512 * 128) {
        int r = i >> 7, c = (i & 127) * 2;
        const float* W = (r < 256) ? &Wk[r * 256 + c] : &Wv[(r - 256) * 256 + c];
        g_Wh[i] = pack_h2(W[0], W[1]);
    }
}

// ---------------------------------------------------------------------------
// K1: (K|V) = W @ x + bias; K: exp + rowsum fused. fp16 MMA.
// 256 thr (8 warps: 4m x 2n), CTA tile 128x128, chunk 32 channels.
// Each CTA processes FOUR n-tiles with the W tile resident (A loaded once):
// grid (4 m-tiles, 32 n-groups, 8 b) = 1024 CTAs -> 3.5 waves at occ 2.
// B: LDG f32 -> cvt f16x2 -> STS, [n][k] stride 20 u32, reg-double-buffered.
// Epilogue: R8-style direct fragment half2 stores.
// ---------------------------------------------------------------------------
#define ASTR      132                            // u32 per A row
#define K1_A_B    (128 * ASTR * 4)               // 67584
#define SBU       20                             // u32 per B row
#define K1_B_B    (128 * SBU * 4)                // 10240 per buffer
#define K1_SMEM   (K1_A_B + 2 * K1_B_B)          // 88064

__global__ void __launch_bounds__(256, 2)
k1_gemm(const float* __restrict__ x,
        const float* __restrict__ bk, const float* __restrict__ bv) {
    extern __shared__ char sm1[];
    const uint32_t smbase = (uint32_t)__cvta_generic_to_shared(sm1);

    const int tid  = threadIdx.x;
    const int wid  = tid >> 5;
    const int lane = tid & 31;
    const int lr   = lane >> 2, lc = lane & 3;
    const int wm   = (wid & 3) * 32;
    const int wn   = (wid >> 2) * 64;

    const int mtile = blockIdx.x;            // 0..3
    const int b     = blockIdx.z;
    const bool isK  = (mtile < 2);
    const int mrow0 = (mtile & 1) * 128;

    const uint32_t* Wh0 = g_Wh + (size_t)(mtile * 128) * 128;

    // ---- issue full-A cp.async (128 rows x 128 u32), once per CTA ----
    #pragma unroll
    for (int p = 0; p < 16; ++p) {
        const int idx = tid + p * 256;
        const int row = idx >> 5, qu = (idx & 31) * 4;
        CPA16(smbase + (uint32_t)(row * ASTR + qu) * 4,
              Wh0 + (size_t)row * 128 + qu);
    }
    CPA_COMMIT();

    const uint32_t* sAu = (const uint32_t*)sm1;
    uint32_t* sB[2] = {(uint32_t*)(sm1 + K1_A_B),
                       (uint32_t*)(sm1 + K1_A_B + K1_B_B)};

    // bias per thread (fixed across n-tiles)
    const float* bias = isK ? bk : bv;
    const float bia[2][2] = {
        {bias[mrow0 + wm + lr],      bias[mrow0 + wm + lr + 8]},
        {bias[mrow0 + wm + 16 + lr], bias[mrow0 + wm + 24 + lr]}};
    __half* gout = isK ? g_Kh : g_Vh;

    CPA_WAIT0();                             // A resident (before first use)

    for (int nt = 0; nt < 4; ++nt) {
        const int n0 = (blockIdx.y * 4 + nt) * 128;
        const float* Xw = x + (size_t)b * CC * NN + n0 + (size_t)(4 * wid) * NN;

        float acc[2][8][4];
        #pragma unroll
        for (int i = 0; i < 2; ++i)
            #pragma unroll
            for (int j = 0; j < 8; ++j)
                #pragma unroll
                for (int t = 0; t < 4; ++t) acc[i][j][t] = 0.0f;

        float bT[4][4];
        #pragma unroll
        for (int i2 = 0; i2 < 4; ++i2) {
            const int nl = i2 * 32 + lane;
            bT[i2][0] = Xw[nl];
            bT[i2][1] = Xw[(size_t)NN + nl];
            bT[i2][2] = Xw[2 * (size_t)NN + nl];
            bT[i2][3] = Xw[3 * (size_t)NN + nl];
        }
        #pragma unroll
        for (int i2 = 0; i2 < 4; ++i2) {
            const int nl = i2 * 32 + lane;
            uint32_t* d = sB[0] + nl * SBU + 2 * wid;
            d[0] = pack_h2(bT[i2][0], bT[i2][1]);
            d[1] = pack_h2(bT[i2][2], bT[i2][3]);
        }
        __syncthreads();

        #pragma unroll
        for (int ic = 0; ic < 8; ++ic) {
            if (ic < 7) {
                const float* Xc = Xw + (size_t)(ic + 1) * 32 * NN;
                #pragma unroll
                for (int i2 = 0; i2 < 4; ++i2) {
                    const int nl = i2 * 32 + lane;
                    bT[i2][0] = Xc[nl];
                    bT[i2][1] = Xc[(size_t)NN + nl];
                    bT[i2][2] = Xc[2 * (size_t)NN + nl];
                    bT[i2][3] = Xc[3 * (size_t)NN + nl];
                }
            }

            const uint32_t* sBu = sB[ic & 1];
            const int abase = ic * 16;
            #pragma unroll
            for (int ks = 0; ks < 2; ++ks) {
                uint32_t a[2][4], bf[8][2];
                #pragma unroll
                for (int i = 0; i < 2; ++i) {
                    const int base = (wm + i * 16 + lr) * ASTR + abase + ks * 8 + lc;
                    a[i][0] = sAu[base];
                    a[i][1] = sAu[base + 8 * ASTR];
                    a[i][2] = sAu[base + 4];
                    a[i][3] = sAu[base + 8 * ASTR + 4];
                }
                #pragma unroll
                for (int j = 0; j < 8; ++j) {
                    const int base = (wn + j * 8 + lr) * SBU + ks * 8 + lc;
                    bf[j][0] = sBu[base];
                    bf[j][1] = sBu[base + 4];
                }
                #pragma unroll
                for (int i = 0; i < 2; ++i)
                    #pragma unroll
                    for (int j = 0; j < 8; ++j) mma_f16(acc[i][j], a[i], bf[j]);
            }

            if (ic < 7) {
                uint32_t* d0 = sB[(ic + 1) & 1];
                #pragma unroll
                for (int i2 = 0; i2 < 4; ++i2) {
                    const int nl = i2 * 32 + lane;
                    uint32_t* d = d0 + nl * SBU + 2 * wid;
                    d[0] = pack_h2(bT[i2][0], bT[i2][1]);
                    d[1] = pack_h2(bT[i2][2], bT[i2][3]);
                }
            }
            __syncthreads();
        }

        // ---- Epilogue (R8 style): bias, exp+rowsum for K, half2 stores ----
        float rs[2][2] = {{0.f, 0.f}, {0.f, 0.f}};
        #pragma unroll
        for (int i = 0; i < 2; ++i) {
            const int ch0 = mrow0 + wm + i * 16 + lr;
            const int ch1 = ch0 + 8;
            const float b0 = bia[i][0], b1 = bia[i][1];
            uint32_t* r0 = (uint32_t*)(gout + ((size_t)b * 256 + ch0) * NN
                                       + n0 + wn + 2 * lc);
            uint32_t* r1 = (uint32_t*)(gout + ((size_t)b * 256 + ch1) * NN
                                       + n0 + wn + 2 * lc);
            #pragma unroll
            for (int j = 0; j < 8; ++j) {
                float v0 = acc[i][j][0] + b0, v1 = acc[i][j][1] + b0;
                float v2 = acc[i][j][2] + b1, v3 = acc[i][j][3] + b1;
                if (isK) {
                    v0 = __expf(v0); v1 = __expf(v1);
                    v2 = __expf(v2); v3 = __expf(v3);
                }
                __half2 h0 = __floats2half2_rn(v0, v1);
                __half2 h1 = __floats2half2_rn(v2, v3);
                if (isK) {       // rowsum of ROUNDED values (cancels in softmax)
                    float2 f0 = __half22float2(h0);
                    float2 f1 = __half22float2(h1);
                    rs[i][0] += f0.x + f0.y;
                    rs[i][1] += f1.x + f1.y;
                }
                r0[j * 4] = *(uint32_t*)&h0;
                r1[j * 4] = *(uint32_t*)&h1;
            }
        }
        if (isK) {
            #pragma unroll
            for (int i = 0; i < 2; ++i)
                #pragma unroll
                for (int h = 0; h < 2; ++h) {
                    float v = rs[i][h];
                    v += __shfl_xor_sync(0xffffffffu, v, 1);
                    v += __shfl_xor_sync(0xffffffffu, v, 2);
                    if (lc == 0) {
                        int ch = mrow0 + wm + i * 16 + lr + h * 8;
                        atomicAdd(&g_s[b * 256 + ch], v);
                    }
                }
        }
    }
}

// ---------------------------------------------------------------------------
// K3: context = (1/s) * expK @ V^T, all fp16 operands, f32 acc.
// 256 thr, warp tile 32x64, CTA 128x128, chunk 32 spatial, 3-stage ring,
// contraction split 8 ways. grid (4 tiles, 8 splits, 8 b). (unchanged R8)
// ---------------------------------------------------------------------------
#define SA3U      20
#define K3_T_B    (128 * SA3U * 4)              // 10240 per tile
#define K3_STG    (2 * K3_T_B)                  // 20480 bytes/stage
#define K3_SMEM   (3 * K3_STG)                  // 61440

__device__ __forceinline__ void k3_prefetch(uint32_t smbase, int st,
                                            const __half* Kb, const __half* Vb,
                                            int c0, int tid) {
    const uint32_t sA = smbase + (uint32_t)(st * K3_STG);
    const uint32_t sB = sA + K3_T_B;
    #pragma unroll
    for (int p = 0; p < 2; ++p) {
        const int idx = tid + p * 256;
        const int row = idx >> 2, qu = (idx & 3) * 4;
        const uint32_t off = (uint32_t)(row * SA3U + qu) * 4;
        CPA16(sA + off, Kb + (size_t)row * NN + c0 + qu * 2);
        CPA16(sB + off, Vb + (size_t)row * NN + c0 + qu * 2);
    }
}

__global__ void __launch_bounds__(256, 2)
k3_context(float* __restrict__ out) {
    extern __shared__ char sm3[];
    const uint32_t smbase = (uint32_t)__cvta_generic_to_shared(sm3);

    const int tid  = threadIdx.x;
    const int wid  = tid >> 5;
    const int lane = tid & 31;
    const int lr   = lane >> 2, lc = lane & 3;
    const int wm   = (wid & 3) * 32;
    const int wn   = (wid >> 2) * 64;

    const int km0 = (blockIdx.x & 1) * 128;
    const int vm0 = (blockIdx.x >> 1) * 128;
    const int nb  = blockIdx.y * 2048;
    const int b   = blockIdx.z;

    const __half* Kb = g_Kh + ((size_t)b * 256 + km0) * NN + nb;
    const __half* Vb = g_Vh + ((size_t)b * 256 + vm0) * NN + nb;

    float acc[2][8][4];
    #pragma unroll
    for (int i = 0; i < 2; ++i)
        #pragma unroll
        for (int j = 0; j < 8; ++j)
            #pragma unroll
            for (int t = 0; t < 4; ++t) acc[i][j][t] = 0.0f;

    k3_prefetch(smbase, 0, Kb, Vb, 0, tid);
    CPA_COMMIT();
    k3_prefetch(smbase, 1, Kb, Vb, 32, tid);
    CPA_COMMIT();

    for (int ic = 0; ic < 64; ++ic) {
        CPA_WAIT1();
        __syncthreads();
        const uint32_t* sAu = (const uint32_t*)(sm3 + (ic % 3) * K3_STG);
        const uint32_t* sBu = (const uint32_t*)(sm3 + (ic % 3) * K3_STG + K3_T_B);

        #pragma unroll
        for (int ks = 0; ks < 2; ++ks) {
            uint32_t a[2][4], bf[8][2];
            #pragma unroll
            for (int i = 0; i < 2; ++i) {
                const int base = (wm + i * 16 + lr) * SA3U + ks * 8 + lc;
                a[i][0] = sAu[base];
                a[i][1] = sAu[base + 8 * SA3U];
                a[i][2] = sAu[base + 4];
                a[i][3] = sAu[base + 8 * SA3U + 4];
            }
            #pragma unroll
            for (int j = 0; j < 8; ++j) {
                const int base = (wn + j * 8 + lr) * SA3U + ks * 8 + lc;
                bf[j][0] = sBu[base];
                bf[j][1] = sBu[base + 4];
            }
            #pragma unroll
            for (int i = 0; i < 2; ++i)
                #pragma unroll
                for (int j = 0; j < 8; ++j) mma_f16(acc[i][j], a[i], bf[j]);
        }

        if (ic + 2 < 64)
            k3_prefetch(smbase, (ic + 2) % 3, Kb, Vb, (ic + 2) * 32, tid);
        CPA_COMMIT();
    }

    #pragma unroll
    for (int i = 0; i < 2; ++i) {
        const int k0r = km0 + wm + i * 16 + lr;
        const int k1r = k0r + 8;
        const float inv0 = 1.0f / g_s[b * 256 + k0r];
        const float inv1 = 1.0f / g_s[b * 256 + k1r];
        float* r0 = out + ((size_t)b * 256 + k0r) * 256 + vm0 + wn + 2 * lc;
        float* r1 = out + ((size_t)b * 256 + k1r) * 256 + vm0 + wn + 2 * lc;
        #pragma unroll
        for (int j = 0; j < 8; ++j) {
            atomicAdd(r0 + j * 8,     acc[i][j][0] * inv0);
            atomicAdd(r0 + j * 8 + 1, acc[i][j][1] * inv0);
            atomicAdd(r1 + j * 8,     acc[i][j][2] * inv1);
            atomicAdd(r1 + j * 8 + 1, acc[i][j][3] * inv1);
        }
    }
}

// ---------------------------------------------------------------------------
// Launch
// ---------------------------------------------------------------------------
extern "C" void kernel_launch(void* const* d_in, const int* in_sizes, int n_in,
                              void* d_out, int out_size) {
    const float* x  = (const float*)d_in[0];
    const float* Wk = (const float*)d_in[1];
    const float* bk = (const float*)d_in[2];
    const float* Wv = (const float*)d_in[3];
    const float* bv = (const float*)d_in[4];
    float* out = (float*)d_out;

    cudaFuncSetAttribute(k1_gemm, cudaFuncAttributeMaxDynamicSharedMemorySize,
                         K1_SMEM);
    cudaFuncSetAttribute(k3_context, cudaFuncAttributeMaxDynamicSharedMemorySize,
                         K3_SMEM);

    k0_prep<<<(out_size + 255) / 256, 256>>>(out, out_size, Wk, Wv);

    dim3 g1(4, 32, BB);
    k1_gemm<<<g1, 256, K1_SMEM>>>(x, bk, bv);

    dim3 g3(4, 8, BB);
    k3_context<<<g3, 256, K3_SMEM>>>(out);
}